// round 15
// baseline (speedup 1.0000x reference)
#include <cuda_runtime.h>
#include <cuda_fp16.h>
#include <cstdint>
#include <math.h>

#define L_   4
#define H_   4
#define B_   2
#define T_   1024
#define D_   1024
#define DFF_ 4096
#define V_   32000
#define M_   (B_*T_)   // 2048 tokens

// ---------------- scratch (static device globals; no allocs allowed) ----------
__device__ float  g_h [M_*D_];          // residual (fp32)
__device__ float  g_part[4*M_*D_];      // split-K partials (fp32)
__device__ __half g_xn[M_*D_];          // LN output (fp16)
__device__ __half g_q [H_*M_*D_];
__device__ __half g_k [H_*M_*D_];
__device__ __half g_v [H_*M_*D_];
__device__ __half g_a [B_*H_*T_*T_];    // scores then softmax probs (fp16, in-place)
__device__ __half g_y [M_*H_*D_];
__device__ __half g_ff[M_*DFF_];
__device__ __half g_logit[(size_t)M_*V_];  // fp16 logits staging
// fp16 weight mirrors
__device__ __half g_wq[L_*H_*D_*D_];
__device__ __half g_wk[L_*H_*D_*D_];
__device__ __half g_wv[L_*H_*D_*D_];
__device__ __half g_wo[L_*H_*D_*D_];
__device__ __half g_w1[L_*D_*DFF_];
__device__ __half g_w2[L_*DFF_*D_];
__device__ __half g_wout[D_*V_];

// ---------------- helpers -------------------------------------------------------
__device__ __forceinline__ uint32_t smem_u32(const void* p) {
    uint32_t a;
    asm("{ .reg .u64 t; cvta.to.shared.u64 t, %1; cvt.u32.u64 %0, t; }" : "=r"(a) : "l"(p));
    return a;
}
__device__ __forceinline__ void cpa16(uint32_t dst, const void* src) {
    asm volatile("cp.async.cg.shared.global [%0], [%1], 16;" :: "r"(dst), "l"(src) : "memory");
}
#define CP_COMMIT() asm volatile("cp.async.commit_group;" ::: "memory")
#define CP_WAIT(n)  asm volatile("cp.async.wait_group %0;" :: "n"(n) : "memory")

__device__ __forceinline__ void mma_f16(float* c, const uint32_t* a, const uint32_t* b) {
    asm volatile("mma.sync.aligned.m16n8k16.row.col.f32.f16.f16.f32 "
        "{%0,%1,%2,%3}, {%4,%5,%6,%7}, {%8,%9}, {%0,%1,%2,%3};"
        : "+f"(c[0]), "+f"(c[1]), "+f"(c[2]), "+f"(c[3])
        : "r"(a[0]), "r"(a[1]), "r"(a[2]), "r"(a[3]), "r"(b[0]), "r"(b[1]));
}
__device__ __forceinline__ void ldsm4(uint32_t* r, uint32_t addr) {
    asm volatile("ldmatrix.sync.aligned.m8n8.x4.shared.b16 {%0,%1,%2,%3}, [%4];"
        : "=r"(r[0]), "=r"(r[1]), "=r"(r[2]), "=r"(r[3]) : "r"(addr));
}
__device__ __forceinline__ void ldsm4t(uint32_t* r, uint32_t addr) {
    asm volatile("ldmatrix.sync.aligned.m8n8.x4.trans.shared.b16 {%0,%1,%2,%3}, [%4];"
        : "=r"(r[0]), "=r"(r[1]), "=r"(r[2]), "=r"(r[3]) : "r"(addr));
}

// ---------------- fast exp on the FMA pipe --------------------------------------
__device__ __forceinline__ float fexp(float x) {
    x = fmaxf(x, -80.f);
    float z = x * 1.4426950408889634f;
    float y = z + 12582912.0f;
    float n = y - 12582912.0f;
    float t = fmaf(n, -0.6931471805599453f, x);
    float p =             0.008333333f;
    p = fmaf(p, t, 0.041666668f);
    p = fmaf(p, t, 0.16666667f);
    p = fmaf(p, t, 0.5f);
    p = fmaf(p, t, 1.0f);
    p = fmaf(p, t, 1.0f);
    int e = __float_as_int(y) - 0x4B400000;
    return p * __int_as_float((127 + e) << 23);
}

// ---------------- block reductions ----------------------------------------------
__device__ __forceinline__ float blockReduceSum(float v) {
    __shared__ float sh[9];
    int lane = threadIdx.x & 31, w = threadIdx.x >> 5;
    #pragma unroll
    for (int o = 16; o; o >>= 1) v += __shfl_xor_sync(0xffffffffu, v, o);
    if (lane == 0) sh[w] = v;
    __syncthreads();
    if (threadIdx.x == 0) {
        float s = 0.f;
        #pragma unroll
        for (int i = 0; i < 8; i++) s += sh[i];
        sh[8] = s;
    }
    __syncthreads();
    float r = sh[8];
    __syncthreads();
    return r;
}
__device__ __forceinline__ float blockReduceMax(float v) {
    __shared__ float sh[9];
    int lane = threadIdx.x & 31, w = threadIdx.x >> 5;
    #pragma unroll
    for (int o = 16; o; o >>= 1) v = fmaxf(v, __shfl_xor_sync(0xffffffffu, v, o));
    if (lane == 0) sh[w] = v;
    __syncthreads();
    if (threadIdx.x == 0) {
        float s = sh[0];
        #pragma unroll
        for (int i = 1; i < 8; i++) s = fmaxf(s, sh[i]);
        sh[8] = s;
    }
    __syncthreads();
    float r = sh[8];
    __syncthreads();
    return r;
}

// ---------------- fp32 -> fp16 convert ------------------------------------------
__global__ void f2h_kernel(const float* __restrict__ s, __half* __restrict__ d, int n) {
    int i = (blockIdx.x * blockDim.x + threadIdx.x) * 8;
    if (i >= n) return;
    float4 v0 = *(const float4*)(s + i);
    float4 v1 = *(const float4*)(s + i + 4);
    __half2 h0 = __floats2half2_rn(v0.x, v0.y);
    __half2 h1 = __floats2half2_rn(v0.z, v0.w);
    __half2 h2 = __floats2half2_rn(v1.x, v1.y);
    __half2 h3 = __floats2half2_rn(v1.z, v1.w);
    uint4 u;
    u.x = *(uint32_t*)&h0; u.y = *(uint32_t*)&h1;
    u.z = *(uint32_t*)&h2; u.w = *(uint32_t*)&h3;
    *(uint4*)(d + i) = u;
}

// ---------------- fused: h += (p0+p1+p2+p3) + bias, then LayerNorm(h) -> xn -------
__global__ void reduce4_ln_kernel(float* __restrict__ h, const float* __restrict__ part,
                                  const float* __restrict__ bias,
                                  __half* __restrict__ out,
                                  const float* __restrict__ g,
                                  const float* __restrict__ b) {
    int m = blockIdx.x;
    int tid = threadIdx.x;
    int c = tid * 4;
    const float* p = part + (size_t)m * D_ + c;
    float4 p0 = *(const float4*)(p);
    float4 p1 = *(const float4*)(p + (size_t)M_ * D_);
    float4 p2 = *(const float4*)(p + 2 * (size_t)M_ * D_);
    float4 p3 = *(const float4*)(p + 3 * (size_t)M_ * D_);
    float4 bb = *(const float4*)(bias + c);
    float4 v = *(const float4*)(h + (size_t)m * D_ + c);
    v.x += p0.x + p1.x + p2.x + p3.x + bb.x;
    v.y += p0.y + p1.y + p2.y + p3.y + bb.y;
    v.z += p0.z + p1.z + p2.z + p3.z + bb.z;
    v.w += p0.w + p1.w + p2.w + p3.w + bb.w;
    *(float4*)(h + (size_t)m * D_ + c) = v;
    float s = v.x + v.y + v.z + v.w;
    s = blockReduceSum(s);
    float mean = s * (1.0f / D_);
    float dx = v.x - mean, dy = v.y - mean, dz = v.z - mean, dw = v.w - mean;
    float q = dx*dx + dy*dy + dz*dz + dw*dw;
    q = blockReduceSum(q);
    float inv = rsqrtf(q * (1.0f / D_) + 1e-5f);
    float4 gg = ((const float4*)g)[tid];
    float4 lb = ((const float4*)b)[tid];
    __half2 h0 = __floats2half2_rn(dx * inv * gg.x + lb.x, dy * inv * gg.y + lb.y);
    __half2 h1 = __floats2half2_rn(dz * inv * gg.z + lb.z, dw * inv * gg.w + lb.w);
    uint2 u; u.x = *(uint32_t*)&h0; u.y = *(uint32_t*)&h1;
    *(uint2*)(out + (size_t)m * D_ + c) = u;
}

// ---------------- embedding ------------------------------------------------------
__global__ void embed_kernel(const int* __restrict__ x,
                             const float* __restrict__ emb,
                             float* __restrict__ h) {
    int m = blockIdx.x;
    int t = m % T_;
    int tok = x[m];
    const float* erow = emb + (size_t)tok * D_;
    float* hrow = h + (size_t)m * D_;
    for (int d = threadIdx.x; d < D_; d += blockDim.x) {
        int i = d >> 1;
        float denom = powf(10000.f, (2.f * (float)i) / (float)D_);
        float ang = (float)t / denom;
        float pe = (d & 1) ? cosf(ang) : sinf(ang);
        hrow[d] = erow[d] + pe;
    }
}

// ---------------- layernorm (fp32 in, fp16 out) ----------------------------------
__global__ void layernorm_kernel(const float* __restrict__ in,
                                 __half* __restrict__ out,
                                 const float* __restrict__ g,
                                 const float* __restrict__ b) {
    int m = blockIdx.x;
    int tid = threadIdx.x;
    const float4* x4 = (const float4*)(in + (size_t)m * D_);
    float4 v = x4[tid];
    float s = v.x + v.y + v.z + v.w;
    s = blockReduceSum(s);
    float mean = s * (1.0f / D_);
    float dx = v.x - mean, dy = v.y - mean, dz = v.z - mean, dw = v.w - mean;
    float q = dx*dx + dy*dy + dz*dz + dw*dw;
    q = blockReduceSum(q);
    float inv = rsqrtf(q * (1.0f / D_) + 1e-5f);
    float4 gg = ((const float4*)g)[tid];
    float4 bb = ((const float4*)b)[tid];
    __half2 h0 = __floats2half2_rn(dx * inv * gg.x + bb.x, dy * inv * gg.y + bb.y);
    __half2 h1 = __floats2half2_rn(dz * inv * gg.z + bb.z, dw * inv * gg.w + bb.w);
    uint2 u; u.x = *(uint32_t*)&h0; u.y = *(uint32_t*)&h1;
    *(uint2*)(out + (size_t)m * D_ + tid * 4) = u;
}

// ---------------- causal softmax, fp16 in-place, clamped to causal extent --------
__global__ void attn_softmax_kernel(__half* __restrict__ A) {
    int r = blockIdx.x;            // 0 .. B*H*T-1
    int t = r % T_;
    int z = r / T_;
    __half* row = A + (size_t)z * T_ * T_ + (size_t)t * T_;
    const float scale = 0.03125f;  // 1/sqrt(1024)
    int tid = threadIdx.x;
    int c4 = tid * 4;
    int klim = ((t >> 7) + 1) << 7;   // AV only reads columns < klim
    bool act = c4 < klim;
    float v[4] = { -INFINITY, -INFINITY, -INFINITY, -INFINITY };
    if (act) {
        uint2 u = *(const uint2*)&row[c4];
        __half2 h01 = *(__half2*)&u.x;
        __half2 h23 = *(__half2*)&u.y;
        v[0] = __low2float(h01);  v[1] = __high2float(h01);
        v[2] = __low2float(h23);  v[3] = __high2float(h23);
        #pragma unroll
        for (int j = 0; j < 4; j++)
            v[j] = (c4 + j <= t) ? v[j] * scale : -INFINITY;
    }
    float lmax = fmaxf(fmaxf(v[0], v[1]), fmaxf(v[2], v[3]));
    float mx = blockReduceMax(lmax);
    float e[4]; float lsum = 0.f;
    #pragma unroll
    for (int j = 0; j < 4; j++) {
        e[j] = (act && c4 + j <= t) ? fexp(v[j] - mx) : 0.f;
        lsum += e[j];
    }
    float sum = blockReduceSum(lsum);
    float invs = 1.0f / sum;
    if (act) {
        __half2 o01 = __floats2half2_rn(e[0] * invs, e[1] * invs);
        __half2 o23 = __floats2half2_rn(e[2] * invs, e[3] * invs);
        uint2 o; o.x = *(uint32_t*)&o01; o.y = *(uint32_t*)&o23;
        *(uint2*)&row[c4] = o;
    }
}

// ---------------- final log-softmax: fp16 logits in, fp32 out --------------------
__global__ void logsoftmax_kernel(const __half* __restrict__ in, float* __restrict__ out) {
    extern __shared__ __half sh16[];          // V_ halves = 64000 B
    const __half* row = in + (size_t)blockIdx.x * V_;
    float* orow = out + (size_t)blockIdx.x * V_;
    int tid = threadIdx.x;
    float lmax = -INFINITY;
    for (int i = tid * 8; i < V_; i += 2048) {
        uint4 u = *(const uint4*)&row[i];
        *(uint4*)&sh16[i] = u;
        const __half2* hp = (const __half2*)&u;
        #pragma unroll
        for (int q = 0; q < 4; q++) {
            float2 f = __half22float2(hp[q]);
            lmax = fmaxf(lmax, fmaxf(f.x, f.y));
        }
    }
    float mx = blockReduceMax(lmax);
    float lsum = 0.f;
    for (int i = tid * 2; i < V_; i += 512) {
        float2 f = __half22float2(*(const __half2*)&sh16[i]);
        lsum += fexp(f.x - mx) + fexp(f.y - mx);
    }
    float sum = blockReduceSum(lsum);
    float lse = logf(sum) + mx;
    for (int i = tid * 8; i < V_; i += 2048) {
        uint4 u = *(const uint4*)&sh16[i];
        const __half2* hp = (const __half2*)&u;
        float4 o0, o1;
        float2 f0 = __half22float2(hp[0]);
        float2 f1 = __half22float2(hp[1]);
        float2 f2 = __half22float2(hp[2]);
        float2 f3 = __half22float2(hp[3]);
        o0.x = f0.x - lse; o0.y = f0.y - lse; o0.z = f1.x - lse; o0.w = f1.y - lse;
        o1.x = f2.x - lse; o1.y = f2.y - lse; o1.z = f3.x - lse; o1.w = f3.y - lse;
        *(float4*)&orow[i]     = o0;
        *(float4*)&orow[i + 4] = o1;
    }
}

// ---------------- fp16 HMMA GEMM body: m16n8k16, 3-stage cp.async ----------------
#define GF_ADDC   1
#define GF_GELU   2
#define GF_CAUSAL 4
#define GF_KLIM   8
#define GF_HALF   16

#define A_BYTES   16384
#define B_BYTES   16384
#define STAGE     (A_BYTES + B_BYTES)
#define NSTAGE    3
#define SMEM_REQ  (NSTAGE * STAGE)

template<bool TRANSB>
__device__ __forceinline__ void gemm_body(
        const __half* __restrict__ A, const __half* __restrict__ B,
        void* __restrict__ Cv, const float* __restrict__ bias,
        int K, int lda, int ldb, int ldc, int bx, int by, int flags) {
    extern __shared__ char sm[];
    const uint32_t smBase = smem_u32(sm);

    const int tid = threadIdx.x;
    const int wid = tid >> 5, lane = tid & 31;
    const int lr = lane >> 2, lc = lane & 3;
    const int wm = wid & 1, wn = wid >> 1;
    const int lxor = lane & 7;

    const int aRowL = ((lane >> 3) & 1) * 8 + (lane & 7);
    const int aSel  = (lane >> 4) & 1;
    const uint32_t aBase = (uint32_t)((wm * 64 + aRowL) * 128);
    const int bRowL = ((lane >> 4) & 1) * 8 + (lane & 7);
    const int bSel  = (lane >> 3) & 1;
    const uint32_t bBase = (uint32_t)((wn * 32 + bRowL) * 128);
    const int tKL   = ((lane >> 3) & 1) * 8 + (lane & 7);
    const int tNSel = (lane >> 4) & 1;
    const int tNBase = wn * 4 + tNSel;

    const int sr  = tid >> 1;
    const int sc4 = (tid & 1) << 2;
    const __half* Arow = A + (size_t)(by * 128 + sr) * lda;
    const __half* Brow = TRANSB ? (B + (size_t)(bx * 128 + sr) * ldb) : nullptr;
    const int bk  = tid >> 2;
    const int bc4 = (tid & 3) << 2;
    const __half* Bk = TRANSB ? nullptr : (B + (size_t)bk * ldb + (size_t)bx * 128);

    auto issue = [&](int kt, int s) {
        uint32_t dA = smBase + s * STAGE;
        uint32_t dB = dA + A_BYTES;
        const __half* a = Arow + kt * 64;
        #pragma unroll
        for (int j = 0; j < 4; j++) {
            int ch = sc4 + j;
            cpa16(dA + (uint32_t)(sr * 128 + ((ch ^ (sr & 7)) << 4)), a + ch * 8);
        }
        if (TRANSB) {
            const __half* b = Brow + kt * 64;
            #pragma unroll
            for (int j = 0; j < 4; j++) {
                int ch = sc4 + j;
                cpa16(dB + (uint32_t)(sr * 128 + ((ch ^ (sr & 7)) << 4)), b + ch * 8);
            }
        } else {
            const __half* b = Bk + (size_t)kt * 64 * ldb;
            #pragma unroll
            for (int j = 0; j < 4; j++) {
                int ch = bc4 + j;
                cpa16(dB + (uint32_t)(bk * 256 + ((ch ^ (bk & 7)) << 4)), b + ch * 8);
            }
        }
        CP_COMMIT();
    };

    float acc[4][4][4];
    #pragma unroll
    for (int i = 0; i < 4; i++)
        #pragma unroll
        for (int j = 0; j < 4; j++)
            #pragma unroll
            for (int q = 0; q < 4; q++) acc[i][j][q] = 0.f;

    auto compute = [&](int s) {
        const uint32_t AbA = smBase + s * STAGE;
        const uint32_t BbA = AbA + A_BYTES;
        #pragma unroll
        for (int ks = 0; ks < 4; ks++) {
            uint32_t a[4][4], b[4][2];
            uint32_t aC = (uint32_t)((((ks << 1) + aSel) ^ lxor) << 4);
            #pragma unroll
            for (int mt = 0; mt < 4; mt++)
                ldsm4(a[mt], AbA + aBase + mt * 2048 + aC);
            if (TRANSB) {
                uint32_t bC = (uint32_t)((((ks << 1) + bSel) ^ lxor) << 4);
                ldsm4(&b[0][0], BbA + bBase + bC);
                ldsm4(&b[2][0], BbA + bBase + 2048 + bC);
            } else {
                uint32_t kRow = (uint32_t)(ks * 16 + tKL) * 256;
                ldsm4t(&b[0][0], BbA + kRow + (uint32_t)(((tNBase + 0) ^ lxor) << 4));
                ldsm4t(&b[2][0], BbA + kRow + (uint32_t)(((tNBase + 2) ^ lxor) << 4));
            }
            #pragma unroll
            for (int mt = 0; mt < 4; mt++)
                #pragma unroll
                for (int nt = 0; nt < 4; nt++)
                    mma_f16(acc[mt][nt], a[mt], b[nt]);
        }
    };

    int ktiles = K >> 6;
    issue(0, 0);
    issue(1, 1);

    for (int kt = 0; kt < ktiles; kt++) {
        int buf = kt % NSTAGE;
        if (kt + 1 < ktiles) { CP_WAIT(1); } else { CP_WAIT(0); }
        __syncthreads();
        // issue next tile BEFORE compute: loads overlap the whole compute phase
        if (kt + 2 < ktiles) issue(kt + 2, (kt + 2) % NSTAGE);
        compute(buf);
    }

    #pragma unroll
    for (int mt = 0; mt < 4; mt++) {
        #pragma unroll
        for (int half = 0; half < 2; half++) {
            int r = by * 128 + wm * 64 + mt * 16 + lr + 8 * half;
            #pragma unroll
            for (int nt = 0; nt < 4; nt++) {
                int cc = bx * 128 + wn * 32 + nt * 8 + 2 * lc;
                float2 v = make_float2(acc[mt][nt][2 * half], acc[mt][nt][2 * half + 1]);
                if (bias) {
                    float2 bb = *(const float2*)&bias[cc];
                    v.x += bb.x; v.y += bb.y;
                }
                if (flags & GF_GELU) {
                    v.x = 0.5f * v.x * (1.0f + erff(v.x * 0.70710678118654752f));
                    v.y = 0.5f * v.y * (1.0f + erff(v.y * 0.70710678118654752f));
                }
                if (flags & GF_HALF) {
                    __half2 hv = __floats2half2_rn(v.x, v.y);
                    *(__half2*)((__half*)Cv + (size_t)r * ldc + cc) = hv;
                } else {
                    float* crow = (float*)Cv + (size_t)r * ldc;
                    if (flags & GF_ADDC) {
                        float2 o = *(const float2*)&crow[cc];
                        v.x += o.x; v.y += o.y;
                    }
                    *(float2*)&crow[cc] = v;
                }
            }
        }
    }
}

// ---------------- generic batched GEMM kernel ---------------------------------------
template<bool TRANSB>
__global__ void __launch_bounds__(256, 2)
hmma_gemm(const __half* __restrict__ A, const __half* __restrict__ B,
          void* __restrict__ C, const float* __restrict__ bias,
          int K, int lda, int ldb, int ldc,
          long sAb, long sAh, long sBb, long sBh, long sCb, long sCh,
          long sBiash, int nH, int flags) {
    int bx = blockIdx.x, by = blockIdx.y;
    if (flags & (GF_CAUSAL | GF_KLIM)) by = (int)gridDim.y - 1 - by;
    if ((flags & GF_CAUSAL) && bx > by) return;
    if (flags & GF_KLIM) K = min(K, (by + 1) * 128);

    int z  = blockIdx.z;
    int zb = z / nH, zh = z % nH;
    A += (size_t)zb * sAb + (size_t)zh * sAh;
    B += (size_t)zb * sBb + (size_t)zh * sBh;
    if (flags & GF_HALF) C = (void*)((__half*)C + (size_t)zb * sCb + (size_t)zh * sCh);
    else                 C = (void*)((float*)C + (size_t)zb * sCb + (size_t)zh * sCh);
    if (bias) bias += (size_t)zh * sBiash;

    gemm_body<TRANSB>(A, B, C, bias, K, lda, ldb, ldc, bx, by, flags);
}

// ---------------- fused QKV kernel (z = 0..3*H-1, sel = z/H) -------------------------
__global__ void __launch_bounds__(256, 2)
qkv_gemm(const __half* __restrict__ A,
         const __half* __restrict__ Wq, const __half* __restrict__ Wk, const __half* __restrict__ Wv,
         const float* __restrict__ bq, const float* __restrict__ bk, const float* __restrict__ bv,
         __half* __restrict__ Cq, __half* __restrict__ Ck, __half* __restrict__ Cv) {
    int z = blockIdx.z;
    int sel = z >> 2;        // H_ == 4
    int zh  = z & 3;
    const __half* W = (sel == 0) ? Wq : (sel == 1) ? Wk : Wv;
    const float* bb = (sel == 0) ? bq : (sel == 1) ? bk : bv;
    __half* C = (sel == 0) ? Cq : (sel == 1) ? Ck : Cv;
    W  += (size_t)zh * D_ * D_;
    bb += (size_t)zh * D_;
    C  += (size_t)zh * (size_t)M_ * D_;
    gemm_body<false>(A, W, (void*)C, bb, D_, D_, D_, D_, blockIdx.x, blockIdx.y, GF_HALF);
}

// ---------------- host-side launcher -------------------------------------------------
static void launch_gemm(bool transB, const __half* A, const __half* B, void* C,
                        const float* bias, int M, int N, int K,
                        int lda, int ldb, int ldc,
                        long sAb, long sAh, long sBb, long sBh,
                        long sCb, long sCh, long sBiash,
                        int nB, int nH, int flags) {
    dim3 grid(N / 128, M / 128, nB * nH);
    if (transB)
        hmma_gemm<true><<<grid, 256, SMEM_REQ>>>(A, B, C, bias, K, lda, ldb, ldc,
                                                 sAb, sAh, sBb, sBh, sCb, sCh, sBiash, nH, flags);
    else
        hmma_gemm<false><<<grid, 256, SMEM_REQ>>>(A, B, C, bias, K, lda, ldb, ldc,
                                                  sAb, sAh, sBb, sBh, sCb, sCh, sBiash, nH, flags);
}

static void launch_f2h_s(const float* s, __half* d, long n, cudaStream_t st) {
    int blocks = (int)((n + 2047) / 2048);
    f2h_kernel<<<blocks, 256, 0, st>>>(s, d, (int)n);
}

extern "C" void kernel_launch(void* const* d_in, const int* in_sizes, int n_in,
                              void* d_out, int out_size) {
    const int*   x         = (const int*)  d_in[0];
    const float* token_emb = (const float*)d_in[1];
    const float* Wq   = (const float*)d_in[2];
    const float* bq   = (const float*)d_in[3];
    const float* Wk   = (const float*)d_in[4];
    const float* bk   = (const float*)d_in[5];
    const float* Wv   = (const float*)d_in[6];
    const float* bv   = (const float*)d_in[7];
    const float* Wo   = (const float*)d_in[8];
    const float* bo   = (const float*)d_in[9];
    const float* ln1g = (const float*)d_in[10];
    const float* ln1b = (const float*)d_in[11];
    const float* ln2g = (const float*)d_in[12];
    const float* ln2b = (const float*)d_in[13];
    const float* W1   = (const float*)d_in[14];
    const float* b1   = (const float*)d_in[15];
    const float* W2   = (const float*)d_in[16];
    const float* b2   = (const float*)d_in[17];
    const float* flng = (const float*)d_in[18];
    const float* flnb = (const float*)d_in[19];
    const float* Wout = (const float*)d_in[20];
    float* out = (float*)d_out;

    cudaFuncSetAttribute(hmma_gemm<false>, cudaFuncAttributeMaxDynamicSharedMemorySize, SMEM_REQ);
    cudaFuncSetAttribute(hmma_gemm<true>,  cudaFuncAttributeMaxDynamicSharedMemorySize, SMEM_REQ);
    cudaFuncSetAttribute(qkv_gemm,         cudaFuncAttributeMaxDynamicSharedMemorySize, SMEM_REQ);
    cudaFuncSetAttribute(logsoftmax_kernel, cudaFuncAttributeMaxDynamicSharedMemorySize, V_ * 2);

    static cudaStream_t s_side = nullptr;
    static cudaEvent_t  e_fork = nullptr, e_join = nullptr;
    if (!s_side) {
        cudaStreamCreateWithFlags(&s_side, cudaStreamNonBlocking);
        cudaEventCreateWithFlags(&e_fork, cudaEventDisableTiming);
        cudaEventCreateWithFlags(&e_join, cudaEventDisableTiming);
    }

    float *ph, *ppart;
    __half *pxn, *pq, *pk, *pv, *pa, *py, *pff, *plog;
    __half *wq, *wk, *wv, *wo, *w1, *w2, *wout;
    cudaGetSymbolAddress((void**)&ph,  g_h);
    cudaGetSymbolAddress((void**)&ppart, g_part);
    cudaGetSymbolAddress((void**)&pxn, g_xn);
    cudaGetSymbolAddress((void**)&pq,  g_q);
    cudaGetSymbolAddress((void**)&pk,  g_k);
    cudaGetSymbolAddress((void**)&pv,  g_v);
    cudaGetSymbolAddress((void**)&pa,  g_a);
    cudaGetSymbolAddress((void**)&py,  g_y);
    cudaGetSymbolAddress((void**)&pff, g_ff);
    cudaGetSymbolAddress((void**)&plog, g_logit);
    cudaGetSymbolAddress((void**)&wq,  g_wq);
    cudaGetSymbolAddress((void**)&wk,  g_wk);
    cudaGetSymbolAddress((void**)&wv,  g_wv);
    cudaGetSymbolAddress((void**)&wo,  g_wo);
    cudaGetSymbolAddress((void**)&w1,  g_w1);
    cudaGetSymbolAddress((void**)&w2,  g_w2);
    cudaGetSymbolAddress((void**)&wout, g_wout);

    const long HDD = (long)H_ * D_ * D_;

    launch_f2h_s(Wq, wq, HDD, 0);
    launch_f2h_s(Wk, wk, HDD, 0);
    launch_f2h_s(Wv, wv, HDD, 0);

    cudaEventRecord(e_fork, 0);
    cudaStreamWaitEvent(s_side, e_fork, 0);
    launch_f2h_s(Wq + HDD, wq + HDD, 3 * HDD, s_side);
    launch_f2h_s(Wk + HDD, wk + HDD, 3 * HDD, s_side);
    launch_f2h_s(Wv + HDD, wv + HDD, 3 * HDD, s_side);
    launch_f2h_s(Wo,   wo,   4 * HDD,               s_side);
    launch_f2h_s(W1,   w1,   (long)L_ * D_ * DFF_,  s_side);
    launch_f2h_s(W2,   w2,   (long)L_ * DFF_ * D_,  s_side);
    launch_f2h_s(Wout, wout, (long)D_ * V_,         s_side);
    cudaEventRecord(e_join, s_side);

    embed_kernel<<<M_, 256>>>(x, token_emb, ph);
    layernorm_kernel<<<M_, 256>>>(ph, pxn, ln1g, ln1b);

    bool joined = false;
    for (int l = 0; l < L_; l++) {
        const long wOff = (long)l * HDD;
        const long bOff = (long)l * H_ * D_;
        {
            dim3 grid(D_ / 128, M_ / 128, 3 * H_);
            qkv_gemm<<<grid, 256, SMEM_REQ>>>(pxn,
                wq + wOff, wk + wOff, wv + wOff,
                bq + bOff, bk + bOff, bv + bOff,
                pq, pk, pv);
        }

        launch_gemm(true, pq, pk, pa, nullptr,
                    T_, T_, D_, D_, D_, T_,
                    (long)T_ * D_, (long)M_ * D_,
                    (long)T_ * D_, (long)M_ * D_,
                    (long)H_ * T_ * T_, (long)T_ * T_,
                    0, B_, H_, GF_CAUSAL | GF_HALF);

        attn_softmax_kernel<<<B_ * H_ * T_, 256>>>(pa);

        launch_gemm(false, pa, pv, py, nullptr,
                    T_, D_, T_, T_, D_, H_ * D_,
                    (long)H_ * T_ * T_, (long)T_ * T_,
                    (long)T_ * D_, (long)M_ * D_,
                    (long)T_ * H_ * D_, (long)D_,
                    0, B_, H_, GF_KLIM | GF_HALF);

        if (!joined) {
            cudaStreamWaitEvent(0, e_join, 0);
            joined = true;
        }

        launch_gemm(false, py, wo + wOff, ppart, nullptr,
                    M_, D_, D_, H_ * D_, D_, D_,
                    0, (long)D_,
                    0, (long)D_ * D_,
                    0, (long)M_ * D_,
                    0, 1, 4, 0);
        reduce4_ln_kernel<<<M_, 256>>>(ph, ppart, bo + (long)l * D_, pxn,
                                       ln2g + (size_t)l * D_, ln2b + (size_t)l * D_);

        launch_gemm(false, pxn, w1 + (long)l * D_ * DFF_, pff, b1 + (long)l * DFF_,
                    M_, DFF_, D_, D_, DFF_, DFF_,
                    0, 0, 0, 0, 0, 0, 0, 1, 1, GF_GELU | GF_HALF);

        launch_gemm(false, pff, w2 + (long)l * DFF_ * D_, ppart, nullptr,
                    M_, D_, D_, DFF_, D_, D_,
                    0, (long)D_,
                    0, (long)D_ * D_,
                    0, (long)M_ * D_,
                    0, 1, 4, 0);
        if (l + 1 < L_)
            reduce4_ln_kernel<<<M_, 256>>>(ph, ppart, b2 + (long)l * D_, pxn,
                                           ln1g + (size_t)(l + 1) * D_, ln1b + (size_t)(l + 1) * D_);
        else
            reduce4_ln_kernel<<<M_, 256>>>(ph, ppart, b2 + (long)l * D_, pxn,
                                           flng, flnb);
    }

    // logits = xn @ Wout -> fp16 staging buffer
    launch_gemm(false, pxn, wout, plog, nullptr,
                M_, V_, D_, D_, V_, V_,
                0, 0, 0, 0, 0, 0, 0, 1, 1, GF_HALF);

    // log-softmax: fp16 in, fp32 out
    logsoftmax_kernel<<<M_, 256, V_ * 2>>>(plog, out);
}

// round 16
// speedup vs baseline: 1.0399x; 1.0399x over previous
#include <cuda_runtime.h>
#include <cuda_fp16.h>
#include <cstdint>
#include <math.h>

#define L_   4
#define H_   4
#define B_   2
#define T_   1024
#define D_   1024
#define DFF_ 4096
#define V_   32000
#define M_   (B_*T_)   // 2048 tokens

// ---------------- scratch (static device globals; no allocs allowed) ----------
__device__ float  g_h [M_*D_];          // residual (fp32)
__device__ float  g_part[4*M_*D_];      // split-K partials (fp32)
__device__ __half g_xn[M_*D_];          // LN output (fp16)
__device__ __half g_q [H_*M_*D_];
__device__ __half g_k [H_*M_*D_];
__device__ __half g_v [H_*M_*D_];
__device__ __half g_a [B_*H_*T_*T_];    // scores then softmax probs (fp16, in-place)
__device__ __half g_y [M_*H_*D_];
__device__ __half g_ff[M_*DFF_];
__device__ __half g_logit[(size_t)M_*V_];  // fp16 logits staging
// fp16 weight mirrors
__device__ __half g_wq[L_*H_*D_*D_];
__device__ __half g_wk[L_*H_*D_*D_];
__device__ __half g_wv[L_*H_*D_*D_];
__device__ __half g_wo[L_*H_*D_*D_];
__device__ __half g_w1[L_*D_*DFF_];
__device__ __half g_w2[L_*DFF_*D_];
__device__ __half g_wout[D_*V_];

// ---------------- helpers -------------------------------------------------------
__device__ __forceinline__ uint32_t smem_u32(const void* p) {
    uint32_t a;
    asm("{ .reg .u64 t; cvta.to.shared.u64 t, %1; cvt.u32.u64 %0, t; }" : "=r"(a) : "l"(p));
    return a;
}
__device__ __forceinline__ void cpa16(uint32_t dst, const void* src) {
    asm volatile("cp.async.cg.shared.global [%0], [%1], 16;" :: "r"(dst), "l"(src) : "memory");
}
#define CP_COMMIT() asm volatile("cp.async.commit_group;" ::: "memory")
#define CP_WAIT(n)  asm volatile("cp.async.wait_group %0;" :: "n"(n) : "memory")

__device__ __forceinline__ void mma_f16(float* c, const uint32_t* a, const uint32_t* b) {
    asm volatile("mma.sync.aligned.m16n8k16.row.col.f32.f16.f16.f32 "
        "{%0,%1,%2,%3}, {%4,%5,%6,%7}, {%8,%9}, {%0,%1,%2,%3};"
        : "+f"(c[0]), "+f"(c[1]), "+f"(c[2]), "+f"(c[3])
        : "r"(a[0]), "r"(a[1]), "r"(a[2]), "r"(a[3]), "r"(b[0]), "r"(b[1]));
}
__device__ __forceinline__ void ldsm4(uint32_t* r, uint32_t addr) {
    asm volatile("ldmatrix.sync.aligned.m8n8.x4.shared.b16 {%0,%1,%2,%3}, [%4];"
        : "=r"(r[0]), "=r"(r[1]), "=r"(r[2]), "=r"(r[3]) : "r"(addr));
}
__device__ __forceinline__ void ldsm4t(uint32_t* r, uint32_t addr) {
    asm volatile("ldmatrix.sync.aligned.m8n8.x4.trans.shared.b16 {%0,%1,%2,%3}, [%4];"
        : "=r"(r[0]), "=r"(r[1]), "=r"(r[2]), "=r"(r[3]) : "r"(addr));
}

// ---------------- fast exp on the FMA pipe --------------------------------------
__device__ __forceinline__ float fexp(float x) {
    x = fmaxf(x, -80.f);
    float z = x * 1.4426950408889634f;
    float y = z + 12582912.0f;
    float n = y - 12582912.0f;
    float t = fmaf(n, -0.6931471805599453f, x);
    float p =             0.008333333f;
    p = fmaf(p, t, 0.041666668f);
    p = fmaf(p, t, 0.16666667f);
    p = fmaf(p, t, 0.5f);
    p = fmaf(p, t, 1.0f);
    p = fmaf(p, t, 1.0f);
    int e = __float_as_int(y) - 0x4B400000;
    return p * __int_as_float((127 + e) << 23);
}

// ---------------- block reductions ----------------------------------------------
__device__ __forceinline__ float blockReduceSum(float v) {
    __shared__ float sh[9];
    int lane = threadIdx.x & 31, w = threadIdx.x >> 5;
    #pragma unroll
    for (int o = 16; o; o >>= 1) v += __shfl_xor_sync(0xffffffffu, v, o);
    if (lane == 0) sh[w] = v;
    __syncthreads();
    if (threadIdx.x == 0) {
        float s = 0.f;
        #pragma unroll
        for (int i = 0; i < 8; i++) s += sh[i];
        sh[8] = s;
    }
    __syncthreads();
    float r = sh[8];
    __syncthreads();
    return r;
}
__device__ __forceinline__ float blockReduceMax(float v) {
    __shared__ float sh[9];
    int lane = threadIdx.x & 31, w = threadIdx.x >> 5;
    #pragma unroll
    for (int o = 16; o; o >>= 1) v = fmaxf(v, __shfl_xor_sync(0xffffffffu, v, o));
    if (lane == 0) sh[w] = v;
    __syncthreads();
    if (threadIdx.x == 0) {
        float s = sh[0];
        #pragma unroll
        for (int i = 1; i < 8; i++) s = fmaxf(s, sh[i]);
        sh[8] = s;
    }
    __syncthreads();
    float r = sh[8];
    __syncthreads();
    return r;
}

// ---------------- fp32 -> fp16 convert ------------------------------------------
__global__ void f2h_kernel(const float* __restrict__ s, __half* __restrict__ d, int n) {
    int i = (blockIdx.x * blockDim.x + threadIdx.x) * 8;
    if (i >= n) return;
    float4 v0 = *(const float4*)(s + i);
    float4 v1 = *(const float4*)(s + i + 4);
    __half2 h0 = __floats2half2_rn(v0.x, v0.y);
    __half2 h1 = __floats2half2_rn(v0.z, v0.w);
    __half2 h2 = __floats2half2_rn(v1.x, v1.y);
    __half2 h3 = __floats2half2_rn(v1.z, v1.w);
    uint4 u;
    u.x = *(uint32_t*)&h0; u.y = *(uint32_t*)&h1;
    u.z = *(uint32_t*)&h2; u.w = *(uint32_t*)&h3;
    *(uint4*)(d + i) = u;
}

// ---------------- fused: h += (p0+p1+p2+p3) + bias, then LayerNorm(h) -> xn -------
__global__ void reduce4_ln_kernel(float* __restrict__ h, const float* __restrict__ part,
                                  const float* __restrict__ bias,
                                  __half* __restrict__ out,
                                  const float* __restrict__ g,
                                  const float* __restrict__ b) {
    int m = blockIdx.x;
    int tid = threadIdx.x;
    int c = tid * 4;
    const float* p = part + (size_t)m * D_ + c;
    float4 p0 = *(const float4*)(p);
    float4 p1 = *(const float4*)(p + (size_t)M_ * D_);
    float4 p2 = *(const float4*)(p + 2 * (size_t)M_ * D_);
    float4 p3 = *(const float4*)(p + 3 * (size_t)M_ * D_);
    float4 bb = *(const float4*)(bias + c);
    float4 v = *(const float4*)(h + (size_t)m * D_ + c);
    v.x += p0.x + p1.x + p2.x + p3.x + bb.x;
    v.y += p0.y + p1.y + p2.y + p3.y + bb.y;
    v.z += p0.z + p1.z + p2.z + p3.z + bb.z;
    v.w += p0.w + p1.w + p2.w + p3.w + bb.w;
    *(float4*)(h + (size_t)m * D_ + c) = v;
    float s = v.x + v.y + v.z + v.w;
    s = blockReduceSum(s);
    float mean = s * (1.0f / D_);
    float dx = v.x - mean, dy = v.y - mean, dz = v.z - mean, dw = v.w - mean;
    float q = dx*dx + dy*dy + dz*dz + dw*dw;
    q = blockReduceSum(q);
    float inv = rsqrtf(q * (1.0f / D_) + 1e-5f);
    float4 gg = ((const float4*)g)[tid];
    float4 lb = ((const float4*)b)[tid];
    __half2 h0 = __floats2half2_rn(dx * inv * gg.x + lb.x, dy * inv * gg.y + lb.y);
    __half2 h1 = __floats2half2_rn(dz * inv * gg.z + lb.z, dw * inv * gg.w + lb.w);
    uint2 u; u.x = *(uint32_t*)&h0; u.y = *(uint32_t*)&h1;
    *(uint2*)(out + (size_t)m * D_ + c) = u;
}

// ---------------- embedding ------------------------------------------------------
__global__ void embed_kernel(const int* __restrict__ x,
                             const float* __restrict__ emb,
                             float* __restrict__ h) {
    int m = blockIdx.x;
    int t = m % T_;
    int tok = x[m];
    const float* erow = emb + (size_t)tok * D_;
    float* hrow = h + (size_t)m * D_;
    for (int d = threadIdx.x; d < D_; d += blockDim.x) {
        int i = d >> 1;
        float denom = powf(10000.f, (2.f * (float)i) / (float)D_);
        float ang = (float)t / denom;
        float pe = (d & 1) ? cosf(ang) : sinf(ang);
        hrow[d] = erow[d] + pe;
    }
}

// ---------------- layernorm (fp32 in, fp16 out) ----------------------------------
__global__ void layernorm_kernel(const float* __restrict__ in,
                                 __half* __restrict__ out,
                                 const float* __restrict__ g,
                                 const float* __restrict__ b) {
    int m = blockIdx.x;
    int tid = threadIdx.x;
    const float4* x4 = (const float4*)(in + (size_t)m * D_);
    float4 v = x4[tid];
    float s = v.x + v.y + v.z + v.w;
    s = blockReduceSum(s);
    float mean = s * (1.0f / D_);
    float dx = v.x - mean, dy = v.y - mean, dz = v.z - mean, dw = v.w - mean;
    float q = dx*dx + dy*dy + dz*dz + dw*dw;
    q = blockReduceSum(q);
    float inv = rsqrtf(q * (1.0f / D_) + 1e-5f);
    float4 gg = ((const float4*)g)[tid];
    float4 bb = ((const float4*)b)[tid];
    __half2 h0 = __floats2half2_rn(dx * inv * gg.x + bb.x, dy * inv * gg.y + bb.y);
    __half2 h1 = __floats2half2_rn(dz * inv * gg.z + bb.z, dw * inv * gg.w + bb.w);
    uint2 u; u.x = *(uint32_t*)&h0; u.y = *(uint32_t*)&h1;
    *(uint2*)(out + (size_t)m * D_ + tid * 4) = u;
}

// ---------------- causal softmax, fp16 in-place, clamped to causal extent --------
__global__ void attn_softmax_kernel(__half* __restrict__ A) {
    int r = blockIdx.x;            // 0 .. B*H*T-1
    int t = r % T_;
    int z = r / T_;
    __half* row = A + (size_t)z * T_ * T_ + (size_t)t * T_;
    const float scale = 0.03125f;  // 1/sqrt(1024)
    int tid = threadIdx.x;
    int c4 = tid * 4;
    int klim = ((t >> 7) + 1) << 7;   // AV only reads columns < klim
    bool act = c4 < klim;
    float v[4] = { -INFINITY, -INFINITY, -INFINITY, -INFINITY };
    if (act) {
        uint2 u = *(const uint2*)&row[c4];
        __half2 h01 = *(__half2*)&u.x;
        __half2 h23 = *(__half2*)&u.y;
        v[0] = __low2float(h01);  v[1] = __high2float(h01);
        v[2] = __low2float(h23);  v[3] = __high2float(h23);
        #pragma unroll
        for (int j = 0; j < 4; j++)
            v[j] = (c4 + j <= t) ? v[j] * scale : -INFINITY;
    }
    float lmax = fmaxf(fmaxf(v[0], v[1]), fmaxf(v[2], v[3]));
    float mx = blockReduceMax(lmax);
    float e[4]; float lsum = 0.f;
    #pragma unroll
    for (int j = 0; j < 4; j++) {
        e[j] = (act && c4 + j <= t) ? fexp(v[j] - mx) : 0.f;
        lsum += e[j];
    }
    float sum = blockReduceSum(lsum);
    float invs = 1.0f / sum;
    if (act) {
        __half2 o01 = __floats2half2_rn(e[0] * invs, e[1] * invs);
        __half2 o23 = __floats2half2_rn(e[2] * invs, e[3] * invs);
        uint2 o; o.x = *(uint32_t*)&o01; o.y = *(uint32_t*)&o23;
        *(uint2*)&row[c4] = o;
    }
}

// ---------------- final log-softmax: fp16 logits in, fp32 out --------------------
__global__ void logsoftmax_kernel(const __half* __restrict__ in, float* __restrict__ out) {
    extern __shared__ __half sh16[];          // V_ halves = 64000 B
    const __half* row = in + (size_t)blockIdx.x * V_;
    float* orow = out + (size_t)blockIdx.x * V_;
    int tid = threadIdx.x;
    float lmax = -INFINITY;
    for (int i = tid * 8; i < V_; i += 2048) {
        uint4 u = *(const uint4*)&row[i];
        *(uint4*)&sh16[i] = u;
        const __half2* hp = (const __half2*)&u;
        #pragma unroll
        for (int q = 0; q < 4; q++) {
            float2 f = __half22float2(hp[q]);
            lmax = fmaxf(lmax, fmaxf(f.x, f.y));
        }
    }
    float mx = blockReduceMax(lmax);
    float lsum = 0.f;
    for (int i = tid * 2; i < V_; i += 512) {
        float2 f = __half22float2(*(const __half2*)&sh16[i]);
        lsum += fexp(f.x - mx) + fexp(f.y - mx);
    }
    float sum = blockReduceSum(lsum);
    float lse = logf(sum) + mx;
    for (int i = tid * 8; i < V_; i += 2048) {
        uint4 u = *(const uint4*)&sh16[i];
        const __half2* hp = (const __half2*)&u;
        float4 o0, o1;
        float2 f0 = __half22float2(hp[0]);
        float2 f1 = __half22float2(hp[1]);
        float2 f2 = __half22float2(hp[2]);
        float2 f3 = __half22float2(hp[3]);
        o0.x = f0.x - lse; o0.y = f0.y - lse; o0.z = f1.x - lse; o0.w = f1.y - lse;
        o1.x = f2.x - lse; o1.y = f2.y - lse; o1.z = f3.x - lse; o1.w = f3.y - lse;
        *(float4*)&orow[i]     = o0;
        *(float4*)&orow[i + 4] = o1;
    }
}

// ---------------- fp16 HMMA GEMM body: m16n8k16, 3-stage cp.async ----------------
#define GF_ADDC   1
#define GF_GELU   2
#define GF_CAUSAL 4
#define GF_KLIM   8
#define GF_HALF   16

#define A_BYTES   16384
#define B_BYTES   16384
#define STAGE     (A_BYTES + B_BYTES)
#define NSTAGE    3
#define SMEM_REQ  (NSTAGE * STAGE)

template<bool TRANSB>
__device__ __forceinline__ void gemm_body(
        const __half* __restrict__ A, const __half* __restrict__ B,
        void* __restrict__ Cv, const float* __restrict__ bias,
        int K, int lda, int ldb, int ldc, int bx, int by, int flags) {
    extern __shared__ char sm[];
    const uint32_t smBase = smem_u32(sm);

    const int tid = threadIdx.x;
    const int wid = tid >> 5, lane = tid & 31;
    const int lr = lane >> 2, lc = lane & 3;
    const int wm = wid & 1, wn = wid >> 1;
    const int lxor = lane & 7;

    const int aRowL = ((lane >> 3) & 1) * 8 + (lane & 7);
    const int aSel  = (lane >> 4) & 1;
    const uint32_t aBase = (uint32_t)((wm * 64 + aRowL) * 128);
    const int bRowL = ((lane >> 4) & 1) * 8 + (lane & 7);
    const int bSel  = (lane >> 3) & 1;
    const uint32_t bBase = (uint32_t)((wn * 32 + bRowL) * 128);
    const int tKL   = ((lane >> 3) & 1) * 8 + (lane & 7);
    const int tNSel = (lane >> 4) & 1;
    const int tNBase = wn * 4 + tNSel;

    const int sr  = tid >> 1;
    const int sc4 = (tid & 1) << 2;
    const __half* Arow = A + (size_t)(by * 128 + sr) * lda;
    const __half* Brow = TRANSB ? (B + (size_t)(bx * 128 + sr) * ldb) : nullptr;
    const int bk  = tid >> 2;
    const int bc4 = (tid & 3) << 2;
    const __half* Bk = TRANSB ? nullptr : (B + (size_t)bk * ldb + (size_t)bx * 128);

    auto issue = [&](int kt, int s) {
        uint32_t dA = smBase + s * STAGE;
        uint32_t dB = dA + A_BYTES;
        const __half* a = Arow + kt * 64;
        #pragma unroll
        for (int j = 0; j < 4; j++) {
            int ch = sc4 + j;
            cpa16(dA + (uint32_t)(sr * 128 + ((ch ^ (sr & 7)) << 4)), a + ch * 8);
        }
        if (TRANSB) {
            const __half* b = Brow + kt * 64;
            #pragma unroll
            for (int j = 0; j < 4; j++) {
                int ch = sc4 + j;
                cpa16(dB + (uint32_t)(sr * 128 + ((ch ^ (sr & 7)) << 4)), b + ch * 8);
            }
        } else {
            const __half* b = Bk + (size_t)kt * 64 * ldb;
            #pragma unroll
            for (int j = 0; j < 4; j++) {
                int ch = bc4 + j;
                cpa16(dB + (uint32_t)(bk * 256 + ((ch ^ (bk & 7)) << 4)), b + ch * 8);
            }
        }
        CP_COMMIT();
    };

    float acc[4][4][4];
    #pragma unroll
    for (int i = 0; i < 4; i++)
        #pragma unroll
        for (int j = 0; j < 4; j++)
            #pragma unroll
            for (int q = 0; q < 4; q++) acc[i][j][q] = 0.f;

    auto compute = [&](int s) {
        const uint32_t AbA = smBase + s * STAGE;
        const uint32_t BbA = AbA + A_BYTES;
        #pragma unroll
        for (int ks = 0; ks < 4; ks++) {
            uint32_t a[4][4], b[4][2];
            uint32_t aC = (uint32_t)((((ks << 1) + aSel) ^ lxor) << 4);
            #pragma unroll
            for (int mt = 0; mt < 4; mt++)
                ldsm4(a[mt], AbA + aBase + mt * 2048 + aC);
            if (TRANSB) {
                uint32_t bC = (uint32_t)((((ks << 1) + bSel) ^ lxor) << 4);
                ldsm4(&b[0][0], BbA + bBase + bC);
                ldsm4(&b[2][0], BbA + bBase + 2048 + bC);
            } else {
                uint32_t kRow = (uint32_t)(ks * 16 + tKL) * 256;
                ldsm4t(&b[0][0], BbA + kRow + (uint32_t)(((tNBase + 0) ^ lxor) << 4));
                ldsm4t(&b[2][0], BbA + kRow + (uint32_t)(((tNBase + 2) ^ lxor) << 4));
            }
            #pragma unroll
            for (int mt = 0; mt < 4; mt++)
                #pragma unroll
                for (int nt = 0; nt < 4; nt++)
                    mma_f16(acc[mt][nt], a[mt], b[nt]);
        }
    };

    int ktiles = K >> 6;
    issue(0, 0);
    issue(1, 1);

    for (int kt = 0; kt < ktiles; kt++) {
        int buf = kt % NSTAGE;
        if (kt + 1 < ktiles) { CP_WAIT(1); } else { CP_WAIT(0); }
        __syncthreads();
        compute(buf);
        if (kt + 2 < ktiles) issue(kt + 2, (kt + 2) % NSTAGE);
    }

    #pragma unroll
    for (int mt = 0; mt < 4; mt++) {
        #pragma unroll
        for (int half = 0; half < 2; half++) {
            int r = by * 128 + wm * 64 + mt * 16 + lr + 8 * half;
            #pragma unroll
            for (int nt = 0; nt < 4; nt++) {
                int cc = bx * 128 + wn * 32 + nt * 8 + 2 * lc;
                float2 v = make_float2(acc[mt][nt][2 * half], acc[mt][nt][2 * half + 1]);
                if (bias) {
                    float2 bb = *(const float2*)&bias[cc];
                    v.x += bb.x; v.y += bb.y;
                }
                if (flags & GF_GELU) {
                    v.x = 0.5f * v.x * (1.0f + erff(v.x * 0.70710678118654752f));
                    v.y = 0.5f * v.y * (1.0f + erff(v.y * 0.70710678118654752f));
                }
                if (flags & GF_HALF) {
                    __half2 hv = __floats2half2_rn(v.x, v.y);
                    *(__half2*)((__half*)Cv + (size_t)r * ldc + cc) = hv;
                } else {
                    float* crow = (float*)Cv + (size_t)r * ldc;
                    if (flags & GF_ADDC) {
                        float2 o = *(const float2*)&crow[cc];
                        v.x += o.x; v.y += o.y;
                    }
                    *(float2*)&crow[cc] = v;
                }
            }
        }
    }
}

// ---------------- generic batched GEMM kernel ---------------------------------------
template<bool TRANSB>
__global__ void __launch_bounds__(256, 2)
hmma_gemm(const __half* __restrict__ A, const __half* __restrict__ B,
          void* __restrict__ C, const float* __restrict__ bias,
          int K, int lda, int ldb, int ldc,
          long sAb, long sAh, long sBb, long sBh, long sCb, long sCh,
          long sBiash, int nH, int flags) {
    int bx = blockIdx.x, by = blockIdx.y;
    if (flags & (GF_CAUSAL | GF_KLIM)) by = (int)gridDim.y - 1 - by;
    if ((flags & GF_CAUSAL) && bx > by) return;
    if (flags & GF_KLIM) K = min(K, (by + 1) * 128);

    int z  = blockIdx.z;
    int zb = z / nH, zh = z % nH;
    A += (size_t)zb * sAb + (size_t)zh * sAh;
    B += (size_t)zb * sBb + (size_t)zh * sBh;
    if (flags & GF_HALF) C = (void*)((__half*)C + (size_t)zb * sCb + (size_t)zh * sCh);
    else                 C = (void*)((float*)C + (size_t)zb * sCb + (size_t)zh * sCh);
    if (bias) bias += (size_t)zh * sBiash;

    gemm_body<TRANSB>(A, B, C, bias, K, lda, ldb, ldc, bx, by, flags);
}

// ---------------- fused QKV kernel (z = 0..3*H-1, sel = z/H) -------------------------
__global__ void __launch_bounds__(256, 2)
qkv_gemm(const __half* __restrict__ A,
         const __half* __restrict__ Wq, const __half* __restrict__ Wk, const __half* __restrict__ Wv,
         const float* __restrict__ bq, const float* __restrict__ bk, const float* __restrict__ bv,
         __half* __restrict__ Cq, __half* __restrict__ Ck, __half* __restrict__ Cv) {
    int z = blockIdx.z;
    int sel = z >> 2;        // H_ == 4
    int zh  = z & 3;
    const __half* W = (sel == 0) ? Wq : (sel == 1) ? Wk : Wv;
    const float* bb = (sel == 0) ? bq : (sel == 1) ? bk : bv;
    __half* C = (sel == 0) ? Cq : (sel == 1) ? Ck : Cv;
    W  += (size_t)zh * D_ * D_;
    bb += (size_t)zh * D_;
    C  += (size_t)zh * (size_t)M_ * D_;
    gemm_body<false>(A, W, (void*)C, bb, D_, D_, D_, D_, blockIdx.x, blockIdx.y, GF_HALF);
}

// ---------------- host-side launcher -------------------------------------------------
static void launch_gemm(bool transB, const __half* A, const __half* B, void* C,
                        const float* bias, int M, int N, int K,
                        int lda, int ldb, int ldc,
                        long sAb, long sAh, long sBb, long sBh,
                        long sCb, long sCh, long sBiash,
                        int nB, int nH, int flags) {
    dim3 grid(N / 128, M / 128, nB * nH);
    if (transB)
        hmma_gemm<true><<<grid, 256, SMEM_REQ>>>(A, B, C, bias, K, lda, ldb, ldc,
                                                 sAb, sAh, sBb, sBh, sCb, sCh, sBiash, nH, flags);
    else
        hmma_gemm<false><<<grid, 256, SMEM_REQ>>>(A, B, C, bias, K, lda, ldb, ldc,
                                                  sAb, sAh, sBb, sBh, sCb, sCh, sBiash, nH, flags);
}

static void launch_f2h_s(const float* s, __half* d, long n, cudaStream_t st) {
    int blocks = (int)((n + 2047) / 2048);
    f2h_kernel<<<blocks, 256, 0, st>>>(s, d, (int)n);
}

extern "C" void kernel_launch(void* const* d_in, const int* in_sizes, int n_in,
                              void* d_out, int out_size) {
    const int*   x         = (const int*)  d_in[0];
    const float* token_emb = (const float*)d_in[1];
    const float* Wq   = (const float*)d_in[2];
    const float* bq   = (const float*)d_in[3];
    const float* Wk   = (const float*)d_in[4];
    const float* bk   = (const float*)d_in[5];
    const float* Wv   = (const float*)d_in[6];
    const float* bv   = (const float*)d_in[7];
    const float* Wo   = (const float*)d_in[8];
    const float* bo   = (const float*)d_in[9];
    const float* ln1g = (const float*)d_in[10];
    const float* ln1b = (const float*)d_in[11];
    const float* ln2g = (const float*)d_in[12];
    const float* ln2b = (const float*)d_in[13];
    const float* W1   = (const float*)d_in[14];
    const float* b1   = (const float*)d_in[15];
    const float* W2   = (const float*)d_in[16];
    const float* b2   = (const float*)d_in[17];
    const float* flng = (const float*)d_in[18];
    const float* flnb = (const float*)d_in[19];
    const float* Wout = (const float*)d_in[20];
    float* out = (float*)d_out;

    cudaFuncSetAttribute(hmma_gemm<false>, cudaFuncAttributeMaxDynamicSharedMemorySize, SMEM_REQ);
    cudaFuncSetAttribute(hmma_gemm<true>,  cudaFuncAttributeMaxDynamicSharedMemorySize, SMEM_REQ);
    cudaFuncSetAttribute(qkv_gemm,         cudaFuncAttributeMaxDynamicSharedMemorySize, SMEM_REQ);
    cudaFuncSetAttribute(logsoftmax_kernel, cudaFuncAttributeMaxDynamicSharedMemorySize, V_ * 2);

    static cudaStream_t s_side = nullptr;
    static cudaEvent_t  e_fork = nullptr, e_join = nullptr;
    if (!s_side) {
        cudaStreamCreateWithFlags(&s_side, cudaStreamNonBlocking);
        cudaEventCreateWithFlags(&e_fork, cudaEventDisableTiming);
        cudaEventCreateWithFlags(&e_join, cudaEventDisableTiming);
    }

    float *ph, *ppart;
    __half *pxn, *pq, *pk, *pv, *pa, *py, *pff, *plog;
    __half *wq, *wk, *wv, *wo, *w1, *w2, *wout;
    cudaGetSymbolAddress((void**)&ph,  g_h);
    cudaGetSymbolAddress((void**)&ppart, g_part);
    cudaGetSymbolAddress((void**)&pxn, g_xn);
    cudaGetSymbolAddress((void**)&pq,  g_q);
    cudaGetSymbolAddress((void**)&pk,  g_k);
    cudaGetSymbolAddress((void**)&pv,  g_v);
    cudaGetSymbolAddress((void**)&pa,  g_a);
    cudaGetSymbolAddress((void**)&py,  g_y);
    cudaGetSymbolAddress((void**)&pff, g_ff);
    cudaGetSymbolAddress((void**)&plog, g_logit);
    cudaGetSymbolAddress((void**)&wq,  g_wq);
    cudaGetSymbolAddress((void**)&wk,  g_wk);
    cudaGetSymbolAddress((void**)&wv,  g_wv);
    cudaGetSymbolAddress((void**)&wo,  g_wo);
    cudaGetSymbolAddress((void**)&w1,  g_w1);
    cudaGetSymbolAddress((void**)&w2,  g_w2);
    cudaGetSymbolAddress((void**)&wout, g_wout);

    const long HDD = (long)H_ * D_ * D_;

    launch_f2h_s(Wq, wq, HDD, 0);
    launch_f2h_s(Wk, wk, HDD, 0);
    launch_f2h_s(Wv, wv, HDD, 0);

    cudaEventRecord(e_fork, 0);
    cudaStreamWaitEvent(s_side, e_fork, 0);
    launch_f2h_s(Wq + HDD, wq + HDD, 3 * HDD, s_side);
    launch_f2h_s(Wk + HDD, wk + HDD, 3 * HDD, s_side);
    launch_f2h_s(Wv + HDD, wv + HDD, 3 * HDD, s_side);
    launch_f2h_s(Wo,   wo,   4 * HDD,               s_side);
    launch_f2h_s(W1,   w1,   (long)L_ * D_ * DFF_,  s_side);
    launch_f2h_s(W2,   w2,   (long)L_ * DFF_ * D_,  s_side);
    launch_f2h_s(Wout, wout, (long)D_ * V_,         s_side);
    cudaEventRecord(e_join, s_side);

    embed_kernel<<<M_, 256>>>(x, token_emb, ph);
    layernorm_kernel<<<M_, 256>>>(ph, pxn, ln1g, ln1b);

    bool joined = false;
    for (int l = 0; l < L_; l++) {
        const long wOff = (long)l * HDD;
        const long bOff = (long)l * H_ * D_;
        {
            dim3 grid(D_ / 128, M_ / 128, 3 * H_);
            qkv_gemm<<<grid, 256, SMEM_REQ>>>(pxn,
                wq + wOff, wk + wOff, wv + wOff,
                bq + bOff, bk + bOff, bv + bOff,
                pq, pk, pv);
        }

        launch_gemm(true, pq, pk, pa, nullptr,
                    T_, T_, D_, D_, D_, T_,
                    (long)T_ * D_, (long)M_ * D_,
                    (long)T_ * D_, (long)M_ * D_,
                    (long)H_ * T_ * T_, (long)T_ * T_,
                    0, B_, H_, GF_CAUSAL | GF_HALF);

        attn_softmax_kernel<<<B_ * H_ * T_, 256>>>(pa);

        launch_gemm(false, pa, pv, py, nullptr,
                    T_, D_, T_, T_, D_, H_ * D_,
                    (long)H_ * T_ * T_, (long)T_ * T_,
                    (long)T_ * D_, (long)M_ * D_,
                    (long)T_ * H_ * D_, (long)D_,
                    0, B_, H_, GF_KLIM | GF_HALF);

        if (!joined) {
            cudaStreamWaitEvent(0, e_join, 0);
            joined = true;
        }

        launch_gemm(false, py, wo + wOff, ppart, nullptr,
                    M_, D_, D_, H_ * D_, D_, D_,
                    0, (long)D_,
                    0, (long)D_ * D_,
                    0, (long)M_ * D_,
                    0, 1, 4, 0);
        reduce4_ln_kernel<<<M_, 256>>>(ph, ppart, bo + (long)l * D_, pxn,
                                       ln2g + (size_t)l * D_, ln2b + (size_t)l * D_);

        launch_gemm(false, pxn, w1 + (long)l * D_ * DFF_, pff, b1 + (long)l * DFF_,
                    M_, DFF_, D_, D_, DFF_, DFF_,
                    0, 0, 0, 0, 0, 0, 0, 1, 1, GF_GELU | GF_HALF);

        launch_gemm(false, pff, w2 + (long)l * DFF_ * D_, ppart, nullptr,
                    M_, D_, D_, DFF_, D_, D_,
                    0, (long)D_,
                    0, (long)D_ * D_,
                    0, (long)M_ * D_,
                    0, 1, 4, 0);
        if (l + 1 < L_)
            reduce4_ln_kernel<<<M_, 256>>>(ph, ppart, b2 + (long)l * D_, pxn,
                                           ln1g + (size_t)(l + 1) * D_, ln1b + (size_t)(l + 1) * D_);
        else
            reduce4_ln_kernel<<<M_, 256>>>(ph, ppart, b2 + (long)l * D_, pxn,
                                           flng, flnb);
    }

    // logits = xn @ Wout -> fp16 staging buffer
    launch_gemm(false, pxn, wout, plog, nullptr,
                M_, V_, D_, D_, V_, V_,
                0, 0, 0, 0, 0, 0, 0, 1, 1, GF_HALF);

    // log-softmax: fp16 in, fp32 out
    logsoftmax_kernel<<<M_, 256, V_ * 2>>>(plog, out);
}

// round 17
// speedup vs baseline: 1.0526x; 1.0122x over previous
#include <cuda_runtime.h>
#include <cuda_fp16.h>
#include <cstdint>
#include <math.h>

#define L_   4
#define H_   4
#define B_   2
#define T_   1024
#define D_   1024
#define DFF_ 4096
#define V_   32000
#define M_   (B_*T_)   // 2048 tokens

// ---------------- scratch (static device globals; no allocs allowed) ----------
__device__ float  g_h [M_*D_];          // residual (fp32)
__device__ float  g_part[4*M_*D_];      // split-K partials (fp32)
__device__ __half g_xn[M_*D_];          // LN output (fp16)
__device__ __half g_q [H_*M_*D_];
__device__ __half g_k [H_*M_*D_];
__device__ __half g_v [H_*M_*D_];
__device__ __half g_a [B_*H_*T_*T_];    // scores then softmax probs (fp16, in-place)
__device__ __half g_y [M_*H_*D_];
__device__ __half g_ff[M_*DFF_];
__device__ __half g_logit[(size_t)M_*V_];  // fp16 logits staging
// fp16 weight mirrors
__device__ __half g_wq[L_*H_*D_*D_];
__device__ __half g_wk[L_*H_*D_*D_];
__device__ __half g_wv[L_*H_*D_*D_];
__device__ __half g_wo[L_*H_*D_*D_];
__device__ __half g_w1[L_*D_*DFF_];
__device__ __half g_w2[L_*DFF_*D_];
__device__ __half g_wout[D_*V_];

// ---------------- helpers -------------------------------------------------------
__device__ __forceinline__ uint32_t smem_u32(const void* p) {
    uint32_t a;
    asm("{ .reg .u64 t; cvta.to.shared.u64 t, %1; cvt.u32.u64 %0, t; }" : "=r"(a) : "l"(p));
    return a;
}
__device__ __forceinline__ void cpa16(uint32_t dst, const void* src) {
    asm volatile("cp.async.cg.shared.global [%0], [%1], 16;" :: "r"(dst), "l"(src) : "memory");
}
#define CP_COMMIT() asm volatile("cp.async.commit_group;" ::: "memory")
#define CP_WAIT(n)  asm volatile("cp.async.wait_group %0;" :: "n"(n) : "memory")

__device__ __forceinline__ void mma_f16(float* c, const uint32_t* a, const uint32_t* b) {
    asm volatile("mma.sync.aligned.m16n8k16.row.col.f32.f16.f16.f32 "
        "{%0,%1,%2,%3}, {%4,%5,%6,%7}, {%8,%9}, {%0,%1,%2,%3};"
        : "+f"(c[0]), "+f"(c[1]), "+f"(c[2]), "+f"(c[3])
        : "r"(a[0]), "r"(a[1]), "r"(a[2]), "r"(a[3]), "r"(b[0]), "r"(b[1]));
}
__device__ __forceinline__ void ldsm4(uint32_t* r, uint32_t addr) {
    asm volatile("ldmatrix.sync.aligned.m8n8.x4.shared.b16 {%0,%1,%2,%3}, [%4];"
        : "=r"(r[0]), "=r"(r[1]), "=r"(r[2]), "=r"(r[3]) : "r"(addr));
}
__device__ __forceinline__ void ldsm4t(uint32_t* r, uint32_t addr) {
    asm volatile("ldmatrix.sync.aligned.m8n8.x4.trans.shared.b16 {%0,%1,%2,%3}, [%4];"
        : "=r"(r[0]), "=r"(r[1]), "=r"(r[2]), "=r"(r[3]) : "r"(addr));
}

// ---------------- fast exp on the FMA pipe --------------------------------------
__device__ __forceinline__ float fexp(float x) {
    x = fmaxf(x, -80.f);
    float z = x * 1.4426950408889634f;
    float y = z + 12582912.0f;
    float n = y - 12582912.0f;
    float t = fmaf(n, -0.6931471805599453f, x);
    float p =             0.008333333f;
    p = fmaf(p, t, 0.041666668f);
    p = fmaf(p, t, 0.16666667f);
    p = fmaf(p, t, 0.5f);
    p = fmaf(p, t, 1.0f);
    p = fmaf(p, t, 1.0f);
    int e = __float_as_int(y) - 0x4B400000;
    return p * __int_as_float((127 + e) << 23);
}

// ---------------- block reductions ----------------------------------------------
__device__ __forceinline__ float blockReduceSum(float v) {
    __shared__ float sh[9];
    int lane = threadIdx.x & 31, w = threadIdx.x >> 5;
    #pragma unroll
    for (int o = 16; o; o >>= 1) v += __shfl_xor_sync(0xffffffffu, v, o);
    if (lane == 0) sh[w] = v;
    __syncthreads();
    if (threadIdx.x == 0) {
        float s = 0.f;
        #pragma unroll
        for (int i = 0; i < 8; i++) s += sh[i];
        sh[8] = s;
    }
    __syncthreads();
    float r = sh[8];
    __syncthreads();
    return r;
}
__device__ __forceinline__ float blockReduceMax(float v) {
    __shared__ float sh[9];
    int lane = threadIdx.x & 31, w = threadIdx.x >> 5;
    #pragma unroll
    for (int o = 16; o; o >>= 1) v = fmaxf(v, __shfl_xor_sync(0xffffffffu, v, o));
    if (lane == 0) sh[w] = v;
    __syncthreads();
    if (threadIdx.x == 0) {
        float s = sh[0];
        #pragma unroll
        for (int i = 1; i < 8; i++) s = fmaxf(s, sh[i]);
        sh[8] = s;
    }
    __syncthreads();
    float r = sh[8];
    __syncthreads();
    return r;
}

// ---------------- fp32 -> fp16 convert ------------------------------------------
__global__ void f2h_kernel(const float* __restrict__ s, __half* __restrict__ d, int n) {
    int i = (blockIdx.x * blockDim.x + threadIdx.x) * 8;
    if (i >= n) return;
    float4 v0 = *(const float4*)(s + i);
    float4 v1 = *(const float4*)(s + i + 4);
    __half2 h0 = __floats2half2_rn(v0.x, v0.y);
    __half2 h1 = __floats2half2_rn(v0.z, v0.w);
    __half2 h2 = __floats2half2_rn(v1.x, v1.y);
    __half2 h3 = __floats2half2_rn(v1.z, v1.w);
    uint4 u;
    u.x = *(uint32_t*)&h0; u.y = *(uint32_t*)&h1;
    u.z = *(uint32_t*)&h2; u.w = *(uint32_t*)&h3;
    *(uint4*)(d + i) = u;
}

// fused 3-array fp32->fp16 (layer-0 Wq/Wk/Wv): one launch instead of three
__global__ void f2h3_kernel(const float* __restrict__ s0, __half* __restrict__ d0,
                            const float* __restrict__ s1, __half* __restrict__ d1,
                            const float* __restrict__ s2, __half* __restrict__ d2,
                            int n, int blocksPer) {
    int sel = blockIdx.x / blocksPer;
    int bid = blockIdx.x % blocksPer;
    const float* s = (sel == 0) ? s0 : (sel == 1) ? s1 : s2;
    __half* d      = (sel == 0) ? d0 : (sel == 1) ? d1 : d2;
    int i = (bid * blockDim.x + threadIdx.x) * 8;
    if (i >= n) return;
    float4 v0 = *(const float4*)(s + i);
    float4 v1 = *(const float4*)(s + i + 4);
    __half2 h0 = __floats2half2_rn(v0.x, v0.y);
    __half2 h1 = __floats2half2_rn(v0.z, v0.w);
    __half2 h2 = __floats2half2_rn(v1.x, v1.y);
    __half2 h3 = __floats2half2_rn(v1.z, v1.w);
    uint4 u;
    u.x = *(uint32_t*)&h0; u.y = *(uint32_t*)&h1;
    u.z = *(uint32_t*)&h2; u.w = *(uint32_t*)&h3;
    *(uint4*)(d + i) = u;
}

// ---------------- fused: h += (p0+p1+p2+p3) + bias, then LayerNorm(h) -> xn -------
__global__ void reduce4_ln_kernel(float* __restrict__ h, const float* __restrict__ part,
                                  const float* __restrict__ bias,
                                  __half* __restrict__ out,
                                  const float* __restrict__ g,
                                  const float* __restrict__ b) {
    int m = blockIdx.x;
    int tid = threadIdx.x;
    int c = tid * 4;
    const float* p = part + (size_t)m * D_ + c;
    float4 p0 = *(const float4*)(p);
    float4 p1 = *(const float4*)(p + (size_t)M_ * D_);
    float4 p2 = *(const float4*)(p + 2 * (size_t)M_ * D_);
    float4 p3 = *(const float4*)(p + 3 * (size_t)M_ * D_);
    float4 bb = *(const float4*)(bias + c);
    float4 v = *(const float4*)(h + (size_t)m * D_ + c);
    v.x += p0.x + p1.x + p2.x + p3.x + bb.x;
    v.y += p0.y + p1.y + p2.y + p3.y + bb.y;
    v.z += p0.z + p1.z + p2.z + p3.z + bb.z;
    v.w += p0.w + p1.w + p2.w + p3.w + bb.w;
    *(float4*)(h + (size_t)m * D_ + c) = v;
    float s = v.x + v.y + v.z + v.w;
    s = blockReduceSum(s);
    float mean = s * (1.0f / D_);
    float dx = v.x - mean, dy = v.y - mean, dz = v.z - mean, dw = v.w - mean;
    float q = dx*dx + dy*dy + dz*dz + dw*dw;
    q = blockReduceSum(q);
    float inv = rsqrtf(q * (1.0f / D_) + 1e-5f);
    float4 gg = ((const float4*)g)[tid];
    float4 lb = ((const float4*)b)[tid];
    __half2 h0 = __floats2half2_rn(dx * inv * gg.x + lb.x, dy * inv * gg.y + lb.y);
    __half2 h1 = __floats2half2_rn(dz * inv * gg.z + lb.z, dw * inv * gg.w + lb.w);
    uint2 u; u.x = *(uint32_t*)&h0; u.y = *(uint32_t*)&h1;
    *(uint2*)(out + (size_t)m * D_ + c) = u;
}

// ---------------- embedding ------------------------------------------------------
__global__ void embed_kernel(const int* __restrict__ x,
                             const float* __restrict__ emb,
                             float* __restrict__ h) {
    int m = blockIdx.x;
    int t = m % T_;
    int tok = x[m];
    const float* erow = emb + (size_t)tok * D_;
    float* hrow = h + (size_t)m * D_;
    for (int d = threadIdx.x; d < D_; d += blockDim.x) {
        int i = d >> 1;
        float denom = powf(10000.f, (2.f * (float)i) / (float)D_);
        float ang = (float)t / denom;
        float pe = (d & 1) ? cosf(ang) : sinf(ang);
        hrow[d] = erow[d] + pe;
    }
}

// ---------------- layernorm (fp32 in, fp16 out) ----------------------------------
__global__ void layernorm_kernel(const float* __restrict__ in,
                                 __half* __restrict__ out,
                                 const float* __restrict__ g,
                                 const float* __restrict__ b) {
    int m = blockIdx.x;
    int tid = threadIdx.x;
    const float4* x4 = (const float4*)(in + (size_t)m * D_);
    float4 v = x4[tid];
    float s = v.x + v.y + v.z + v.w;
    s = blockReduceSum(s);
    float mean = s * (1.0f / D_);
    float dx = v.x - mean, dy = v.y - mean, dz = v.z - mean, dw = v.w - mean;
    float q = dx*dx + dy*dy + dz*dz + dw*dw;
    q = blockReduceSum(q);
    float inv = rsqrtf(q * (1.0f / D_) + 1e-5f);
    float4 gg = ((const float4*)g)[tid];
    float4 bb = ((const float4*)b)[tid];
    __half2 h0 = __floats2half2_rn(dx * inv * gg.x + bb.x, dy * inv * gg.y + bb.y);
    __half2 h1 = __floats2half2_rn(dz * inv * gg.z + bb.z, dw * inv * gg.w + bb.w);
    uint2 u; u.x = *(uint32_t*)&h0; u.y = *(uint32_t*)&h1;
    *(uint2*)(out + (size_t)m * D_ + tid * 4) = u;
}

// ---------------- causal softmax, fp16 in-place, clamped to causal extent --------
__global__ void attn_softmax_kernel(__half* __restrict__ A) {
    int r = blockIdx.x;            // 0 .. B*H*T-1
    int t = r % T_;
    int z = r / T_;
    __half* row = A + (size_t)z * T_ * T_ + (size_t)t * T_;
    const float scale = 0.03125f;  // 1/sqrt(1024)
    int tid = threadIdx.x;
    int c4 = tid * 4;
    int klim = ((t >> 7) + 1) << 7;   // AV only reads columns < klim
    bool act = c4 < klim;
    float v[4] = { -INFINITY, -INFINITY, -INFINITY, -INFINITY };
    if (act) {
        uint2 u = *(const uint2*)&row[c4];
        __half2 h01 = *(__half2*)&u.x;
        __half2 h23 = *(__half2*)&u.y;
        v[0] = __low2float(h01);  v[1] = __high2float(h01);
        v[2] = __low2float(h23);  v[3] = __high2float(h23);
        #pragma unroll
        for (int j = 0; j < 4; j++)
            v[j] = (c4 + j <= t) ? v[j] * scale : -INFINITY;
    }
    float lmax = fmaxf(fmaxf(v[0], v[1]), fmaxf(v[2], v[3]));
    float mx = blockReduceMax(lmax);
    float e[4]; float lsum = 0.f;
    #pragma unroll
    for (int j = 0; j < 4; j++) {
        e[j] = (act && c4 + j <= t) ? fexp(v[j] - mx) : 0.f;
        lsum += e[j];
    }
    float sum = blockReduceSum(lsum);
    float invs = 1.0f / sum;
    if (act) {
        __half2 o01 = __floats2half2_rn(e[0] * invs, e[1] * invs);
        __half2 o23 = __floats2half2_rn(e[2] * invs, e[3] * invs);
        uint2 o; o.x = *(uint32_t*)&o01; o.y = *(uint32_t*)&o23;
        *(uint2*)&row[c4] = o;
    }
}

// ---------------- final log-softmax: fp16 logits in, fp32 out --------------------
__global__ void logsoftmax_kernel(const __half* __restrict__ in, float* __restrict__ out) {
    extern __shared__ __half sh16[];          // V_ halves = 64000 B
    const __half* row = in + (size_t)blockIdx.x * V_;
    float* orow = out + (size_t)blockIdx.x * V_;
    int tid = threadIdx.x;
    float lmax = -INFINITY;
    for (int i = tid * 8; i < V_; i += 2048) {
        uint4 u = *(const uint4*)&row[i];
        *(uint4*)&sh16[i] = u;
        const __half2* hp = (const __half2*)&u;
        #pragma unroll
        for (int q = 0; q < 4; q++) {
            float2 f = __half22float2(hp[q]);
            lmax = fmaxf(lmax, fmaxf(f.x, f.y));
        }
    }
    float mx = blockReduceMax(lmax);
    float lsum = 0.f;
    for (int i = tid * 2; i < V_; i += 512) {
        float2 f = __half22float2(*(const __half2*)&sh16[i]);
        lsum += fexp(f.x - mx) + fexp(f.y - mx);
    }
    float sum = blockReduceSum(lsum);
    float lse = logf(sum) + mx;
    for (int i = tid * 8; i < V_; i += 2048) {
        uint4 u = *(const uint4*)&sh16[i];
        const __half2* hp = (const __half2*)&u;
        float4 o0, o1;
        float2 f0 = __half22float2(hp[0]);
        float2 f1 = __half22float2(hp[1]);
        float2 f2 = __half22float2(hp[2]);
        float2 f3 = __half22float2(hp[3]);
        o0.x = f0.x - lse; o0.y = f0.y - lse; o0.z = f1.x - lse; o0.w = f1.y - lse;
        o1.x = f2.x - lse; o1.y = f2.y - lse; o1.z = f3.x - lse; o1.w = f3.y - lse;
        *(float4*)&orow[i]     = o0;
        *(float4*)&orow[i + 4] = o1;
    }
}

// ---------------- fp16 HMMA GEMM body: m16n8k16, 3-stage cp.async ----------------
#define GF_ADDC   1
#define GF_GELU   2
#define GF_CAUSAL 4
#define GF_KLIM   8
#define GF_HALF   16

#define A_BYTES   16384
#define B_BYTES   16384
#define STAGE     (A_BYTES + B_BYTES)
#define NSTAGE    3
#define SMEM_REQ  (NSTAGE * STAGE)

template<bool TRANSB>
__device__ __forceinline__ void gemm_body(
        const __half* __restrict__ A, const __half* __restrict__ B,
        void* __restrict__ Cv, const float* __restrict__ bias,
        int K, int lda, int ldb, int ldc, int bx, int by, int flags) {
    extern __shared__ char sm[];
    const uint32_t smBase = smem_u32(sm);

    const int tid = threadIdx.x;
    const int wid = tid >> 5, lane = tid & 31;
    const int lr = lane >> 2, lc = lane & 3;
    const int wm = wid & 1, wn = wid >> 1;
    const int lxor = lane & 7;

    const int aRowL = ((lane >> 3) & 1) * 8 + (lane & 7);
    const int aSel  = (lane >> 4) & 1;
    const uint32_t aBase = (uint32_t)((wm * 64 + aRowL) * 128);
    const int bRowL = ((lane >> 4) & 1) * 8 + (lane & 7);
    const int bSel  = (lane >> 3) & 1;
    const uint32_t bBase = (uint32_t)((wn * 32 + bRowL) * 128);
    const int tKL   = ((lane >> 3) & 1) * 8 + (lane & 7);
    const int tNSel = (lane >> 4) & 1;
    const int tNBase = wn * 4 + tNSel;

    const int sr  = tid >> 1;
    const int sc4 = (tid & 1) << 2;
    const __half* Arow = A + (size_t)(by * 128 + sr) * lda;
    const __half* Brow = TRANSB ? (B + (size_t)(bx * 128 + sr) * ldb) : nullptr;
    const int bk  = tid >> 2;
    const int bc4 = (tid & 3) << 2;
    const __half* Bk = TRANSB ? nullptr : (B + (size_t)bk * ldb + (size_t)bx * 128);

    auto issue = [&](int kt, int s) {
        uint32_t dA = smBase + s * STAGE;
        uint32_t dB = dA + A_BYTES;
        const __half* a = Arow + kt * 64;
        #pragma unroll
        for (int j = 0; j < 4; j++) {
            int ch = sc4 + j;
            cpa16(dA + (uint32_t)(sr * 128 + ((ch ^ (sr & 7)) << 4)), a + ch * 8);
        }
        if (TRANSB) {
            const __half* b = Brow + kt * 64;
            #pragma unroll
            for (int j = 0; j < 4; j++) {
                int ch = sc4 + j;
                cpa16(dB + (uint32_t)(sr * 128 + ((ch ^ (sr & 7)) << 4)), b + ch * 8);
            }
        } else {
            const __half* b = Bk + (size_t)kt * 64 * ldb;
            #pragma unroll
            for (int j = 0; j < 4; j++) {
                int ch = bc4 + j;
                cpa16(dB + (uint32_t)(bk * 256 + ((ch ^ (bk & 7)) << 4)), b + ch * 8);
            }
        }
        CP_COMMIT();
    };

    float acc[4][4][4];
    #pragma unroll
    for (int i = 0; i < 4; i++)
        #pragma unroll
        for (int j = 0; j < 4; j++)
            #pragma unroll
            for (int q = 0; q < 4; q++) acc[i][j][q] = 0.f;

    auto compute = [&](int s) {
        const uint32_t AbA = smBase + s * STAGE;
        const uint32_t BbA = AbA + A_BYTES;
        #pragma unroll
        for (int ks = 0; ks < 4; ks++) {
            uint32_t a[4][4], b[4][2];
            uint32_t aC = (uint32_t)((((ks << 1) + aSel) ^ lxor) << 4);
            #pragma unroll
            for (int mt = 0; mt < 4; mt++)
                ldsm4(a[mt], AbA + aBase + mt * 2048 + aC);
            if (TRANSB) {
                uint32_t bC = (uint32_t)((((ks << 1) + bSel) ^ lxor) << 4);
                ldsm4(&b[0][0], BbA + bBase + bC);
                ldsm4(&b[2][0], BbA + bBase + 2048 + bC);
            } else {
                uint32_t kRow = (uint32_t)(ks * 16 + tKL) * 256;
                ldsm4t(&b[0][0], BbA + kRow + (uint32_t)(((tNBase + 0) ^ lxor) << 4));
                ldsm4t(&b[2][0], BbA + kRow + (uint32_t)(((tNBase + 2) ^ lxor) << 4));
            }
            #pragma unroll
            for (int mt = 0; mt < 4; mt++)
                #pragma unroll
                for (int nt = 0; nt < 4; nt++)
                    mma_f16(acc[mt][nt], a[mt], b[nt]);
        }
    };

    int ktiles = K >> 6;
    issue(0, 0);
    issue(1, 1);

    for (int kt = 0; kt < ktiles; kt++) {
        int buf = kt % NSTAGE;
        if (kt + 1 < ktiles) { CP_WAIT(1); } else { CP_WAIT(0); }
        __syncthreads();
        compute(buf);
        if (kt + 2 < ktiles) issue(kt + 2, (kt + 2) % NSTAGE);
    }

    #pragma unroll
    for (int mt = 0; mt < 4; mt++) {
        #pragma unroll
        for (int half = 0; half < 2; half++) {
            int r = by * 128 + wm * 64 + mt * 16 + lr + 8 * half;
            #pragma unroll
            for (int nt = 0; nt < 4; nt++) {
                int cc = bx * 128 + wn * 32 + nt * 8 + 2 * lc;
                float2 v = make_float2(acc[mt][nt][2 * half], acc[mt][nt][2 * half + 1]);
                if (bias) {
                    float2 bb = *(const float2*)&bias[cc];
                    v.x += bb.x; v.y += bb.y;
                }
                if (flags & GF_GELU) {
                    v.x = 0.5f * v.x * (1.0f + erff(v.x * 0.70710678118654752f));
                    v.y = 0.5f * v.y * (1.0f + erff(v.y * 0.70710678118654752f));
                }
                if (flags & GF_HALF) {
                    __half2 hv = __floats2half2_rn(v.x, v.y);
                    *(__half2*)((__half*)Cv + (size_t)r * ldc + cc) = hv;
                } else {
                    float* crow = (float*)Cv + (size_t)r * ldc;
                    if (flags & GF_ADDC) {
                        float2 o = *(const float2*)&crow[cc];
                        v.x += o.x; v.y += o.y;
                    }
                    *(float2*)&crow[cc] = v;
                }
            }
        }
    }
}

// ---------------- generic batched GEMM kernel ---------------------------------------
template<bool TRANSB>
__global__ void __launch_bounds__(256, 2)
hmma_gemm(const __half* __restrict__ A, const __half* __restrict__ B,
          void* __restrict__ C, const float* __restrict__ bias,
          int K, int lda, int ldb, int ldc,
          long sAb, long sAh, long sBb, long sBh, long sCb, long sCh,
          long sBiash, int nH, int flags) {
    int bx = blockIdx.x, by = blockIdx.y;
    if (flags & (GF_CAUSAL | GF_KLIM)) by = (int)gridDim.y - 1 - by;
    if ((flags & GF_CAUSAL) && bx > by) return;
    if (flags & GF_KLIM) K = min(K, (by + 1) * 128);

    int z  = blockIdx.z;
    int zb = z / nH, zh = z % nH;
    A += (size_t)zb * sAb + (size_t)zh * sAh;
    B += (size_t)zb * sBb + (size_t)zh * sBh;
    if (flags & GF_HALF) C = (void*)((__half*)C + (size_t)zb * sCb + (size_t)zh * sCh);
    else                 C = (void*)((float*)C + (size_t)zb * sCb + (size_t)zh * sCh);
    if (bias) bias += (size_t)zh * sBiash;

    gemm_body<TRANSB>(A, B, C, bias, K, lda, ldb, ldc, bx, by, flags);
}

// ---------------- fused QKV kernel (z = 0..3*H-1, sel = z/H) -------------------------
__global__ void __launch_bounds__(256, 2)
qkv_gemm(const __half* __restrict__ A,
         const __half* __restrict__ Wq, const __half* __restrict__ Wk, const __half* __restrict__ Wv,
         const float* __restrict__ bq, const float* __restrict__ bk, const float* __restrict__ bv,
         __half* __restrict__ Cq, __half* __restrict__ Ck, __half* __restrict__ Cv) {
    int z = blockIdx.z;
    int sel = z >> 2;        // H_ == 4
    int zh  = z & 3;
    const __half* W = (sel == 0) ? Wq : (sel == 1) ? Wk : Wv;
    const float* bb = (sel == 0) ? bq : (sel == 1) ? bk : bv;
    __half* C = (sel == 0) ? Cq : (sel == 1) ? Ck : Cv;
    W  += (size_t)zh * D_ * D_;
    bb += (size_t)zh * D_;
    C  += (size_t)zh * (size_t)M_ * D_;
    gemm_body<false>(A, W, (void*)C, bb, D_, D_, D_, D_, blockIdx.x, blockIdx.y, GF_HALF);
}

// ---------------- host-side launcher -------------------------------------------------
static void launch_gemm(bool transB, const __half* A, const __half* B, void* C,
                        const float* bias, int M, int N, int K,
                        int lda, int ldb, int ldc,
                        long sAb, long sAh, long sBb, long sBh,
                        long sCb, long sCh, long sBiash,
                        int nB, int nH, int flags) {
    dim3 grid(N / 128, M / 128, nB * nH);
    if (transB)
        hmma_gemm<true><<<grid, 256, SMEM_REQ>>>(A, B, C, bias, K, lda, ldb, ldc,
                                                 sAb, sAh, sBb, sBh, sCb, sCh, sBiash, nH, flags);
    else
        hmma_gemm<false><<<grid, 256, SMEM_REQ>>>(A, B, C, bias, K, lda, ldb, ldc,
                                                  sAb, sAh, sBb, sBh, sCb, sCh, sBiash, nH, flags);
}

static void launch_f2h_s(const float* s, __half* d, long n, cudaStream_t st) {
    int blocks = (int)((n + 2047) / 2048);
    f2h_kernel<<<blocks, 256, 0, st>>>(s, d, (int)n);
}

extern "C" void kernel_launch(void* const* d_in, const int* in_sizes, int n_in,
                              void* d_out, int out_size) {
    const int*   x         = (const int*)  d_in[0];
    const float* token_emb = (const float*)d_in[1];
    const float* Wq   = (const float*)d_in[2];
    const float* bq   = (const float*)d_in[3];
    const float* Wk   = (const float*)d_in[4];
    const float* bk   = (const float*)d_in[5];
    const float* Wv   = (const float*)d_in[6];
    const float* bv   = (const float*)d_in[7];
    const float* Wo   = (const float*)d_in[8];
    const float* bo   = (const float*)d_in[9];
    const float* ln1g = (const float*)d_in[10];
    const float* ln1b = (const float*)d_in[11];
    const float* ln2g = (const float*)d_in[12];
    const float* ln2b = (const float*)d_in[13];
    const float* W1   = (const float*)d_in[14];
    const float* b1   = (const float*)d_in[15];
    const float* W2   = (const float*)d_in[16];
    const float* b2   = (const float*)d_in[17];
    const float* flng = (const float*)d_in[18];
    const float* flnb = (const float*)d_in[19];
    const float* Wout = (const float*)d_in[20];
    float* out = (float*)d_out;

    cudaFuncSetAttribute(hmma_gemm<false>, cudaFuncAttributeMaxDynamicSharedMemorySize, SMEM_REQ);
    cudaFuncSetAttribute(hmma_gemm<true>,  cudaFuncAttributeMaxDynamicSharedMemorySize, SMEM_REQ);
    cudaFuncSetAttribute(qkv_gemm,         cudaFuncAttributeMaxDynamicSharedMemorySize, SMEM_REQ);
    cudaFuncSetAttribute(logsoftmax_kernel, cudaFuncAttributeMaxDynamicSharedMemorySize, V_ * 2);

    static cudaStream_t s_side = nullptr, s_emb = nullptr;
    static cudaEvent_t  e_fork = nullptr, e_join = nullptr, e_emb = nullptr;
    if (!s_side) {
        cudaStreamCreateWithFlags(&s_side, cudaStreamNonBlocking);
        cudaStreamCreateWithFlags(&s_emb,  cudaStreamNonBlocking);
        cudaEventCreateWithFlags(&e_fork, cudaEventDisableTiming);
        cudaEventCreateWithFlags(&e_join, cudaEventDisableTiming);
        cudaEventCreateWithFlags(&e_emb,  cudaEventDisableTiming);
    }

    float *ph, *ppart;
    __half *pxn, *pq, *pk, *pv, *pa, *py, *pff, *plog;
    __half *wq, *wk, *wv, *wo, *w1, *w2, *wout;
    cudaGetSymbolAddress((void**)&ph,  g_h);
    cudaGetSymbolAddress((void**)&ppart, g_part);
    cudaGetSymbolAddress((void**)&pxn, g_xn);
    cudaGetSymbolAddress((void**)&pq,  g_q);
    cudaGetSymbolAddress((void**)&pk,  g_k);
    cudaGetSymbolAddress((void**)&pv,  g_v);
    cudaGetSymbolAddress((void**)&pa,  g_a);
    cudaGetSymbolAddress((void**)&py,  g_y);
    cudaGetSymbolAddress((void**)&pff, g_ff);
    cudaGetSymbolAddress((void**)&plog, g_logit);
    cudaGetSymbolAddress((void**)&wq,  g_wq);
    cudaGetSymbolAddress((void**)&wk,  g_wk);
    cudaGetSymbolAddress((void**)&wv,  g_wv);
    cudaGetSymbolAddress((void**)&wo,  g_wo);
    cudaGetSymbolAddress((void**)&w1,  g_w1);
    cudaGetSymbolAddress((void**)&w2,  g_w2);
    cudaGetSymbolAddress((void**)&wout, g_wout);

    const long HDD = (long)H_ * D_ * D_;   // per-layer QKV weight slice
    const int  HDD_BLOCKS = (int)((HDD + 2047) / 2048);

    // fork both side streams from the main stream head
    cudaEventRecord(e_fork, 0);
    cudaStreamWaitEvent(s_side, e_fork, 0);
    cudaStreamWaitEvent(s_emb,  e_fork, 0);

    // main: ONE launch converting layer-0 Wq/Wk/Wv
    f2h3_kernel<<<3 * HDD_BLOCKS, 256>>>(Wq, wq, Wk, wk, Wv, wv, (int)HDD, HDD_BLOCKS);

    // side stream: remaining weight conversions (layers 1-3 QKV, Wo, W1, W2, Wout)
    launch_f2h_s(Wq + HDD, wq + HDD, 3 * HDD, s_side);
    launch_f2h_s(Wk + HDD, wk + HDD, 3 * HDD, s_side);
    launch_f2h_s(Wv + HDD, wv + HDD, 3 * HDD, s_side);
    launch_f2h_s(Wo,   wo,   4 * HDD,               s_side);
    launch_f2h_s(W1,   w1,   (long)L_ * D_ * DFF_,  s_side);
    launch_f2h_s(W2,   w2,   (long)L_ * DFF_ * D_,  s_side);
    launch_f2h_s(Wout, wout, (long)D_ * V_,         s_side);
    cudaEventRecord(e_join, s_side);

    // embed stream: embedding + LN1(layer 0), concurrent with f2h3
    embed_kernel<<<M_, 256, 0, s_emb>>>(x, token_emb, ph);
    layernorm_kernel<<<M_, 256, 0, s_emb>>>(ph, pxn, ln1g, ln1b);
    cudaEventRecord(e_emb, s_emb);

    // main waits for xn before first QKV (f2h3 already done on main in-order)
    cudaStreamWaitEvent(0, e_emb, 0);

    bool joined = false;
    for (int l = 0; l < L_; l++) {
        const long wOff = (long)l * HDD;
        const long bOff = (long)l * H_ * D_;
        {
            dim3 grid(D_ / 128, M_ / 128, 3 * H_);
            qkv_gemm<<<grid, 256, SMEM_REQ>>>(pxn,
                wq + wOff, wk + wOff, wv + wOff,
                bq + bOff, bk + bOff, bv + bOff,
                pq, pk, pv);
        }

        launch_gemm(true, pq, pk, pa, nullptr,
                    T_, T_, D_, D_, D_, T_,
                    (long)T_ * D_, (long)M_ * D_,
                    (long)T_ * D_, (long)M_ * D_,
                    (long)H_ * T_ * T_, (long)T_ * T_,
                    0, B_, H_, GF_CAUSAL | GF_HALF);

        attn_softmax_kernel<<<B_ * H_ * T_, 256>>>(pa);

        launch_gemm(false, pa, pv, py, nullptr,
                    T_, D_, T_, T_, D_, H_ * D_,
                    (long)H_ * T_ * T_, (long)T_ * T_,
                    (long)T_ * D_, (long)M_ * D_,
                    (long)T_ * H_ * D_, (long)D_,
                    0, B_, H_, GF_KLIM | GF_HALF);

        if (!joined) {
            cudaStreamWaitEvent(0, e_join, 0);
            joined = true;
        }

        launch_gemm(false, py, wo + wOff, ppart, nullptr,
                    M_, D_, D_, H_ * D_, D_, D_,
                    0, (long)D_,
                    0, (long)D_ * D_,
                    0, (long)M_ * D_,
                    0, 1, 4, 0);
        reduce4_ln_kernel<<<M_, 256>>>(ph, ppart, bo + (long)l * D_, pxn,
                                       ln2g + (size_t)l * D_, ln2b + (size_t)l * D_);

        launch_gemm(false, pxn, w1 + (long)l * D_ * DFF_, pff, b1 + (long)l * DFF_,
                    M_, DFF_, D_, D_, DFF_, DFF_,
                    0, 0, 0, 0, 0, 0, 0, 1, 1, GF_GELU | GF_HALF);

        launch_gemm(false, pff, w2 + (long)l * DFF_ * D_, ppart, nullptr,
                    M_, D_, D_, DFF_, D_, D_,
                    0, (long)D_,
                    0, (long)D_ * D_,
                    0, (long)M_ * D_,
                    0, 1, 4, 0);
        if (l + 1 < L_)
            reduce4_ln_kernel<<<M_, 256>>>(ph, ppart, b2 + (long)l * D_, pxn,
                                           ln1g + (size_t)(l + 1) * D_, ln1b + (size_t)(l + 1) * D_);
        else
            reduce4_ln_kernel<<<M_, 256>>>(ph, ppart, b2 + (long)l * D_, pxn,
                                           flng, flnb);
    }

    // logits = xn @ Wout -> fp16 staging buffer
    launch_gemm(false, pxn, wout, plog, nullptr,
                M_, V_, D_, D_, V_, V_,
                0, 0, 0, 0, 0, 0, 0, 1, 1, GF_HALF);

    // log-softmax: fp16 in, fp32 out
    logsoftmax_kernel<<<M_, 256, V_ * 2>>>(plog, out);
}